// round 5
// baseline (speedup 1.0000x reference)
#include <cuda_runtime.h>
#include <cuda_bf16.h>
#include <math_constants.h>

// Problem constants
#define L_TOK   343
#define N_WIN   64
#define N_HEAD  12
#define HEAD_D  32
#define DIM     384
#define QKV_N   1152
#define TBL_SZ  2197
#define M_ROWS  (N_WIN * L_TOK)          // 21952
#define SCALE_Q 0.17677669529663687f     // 32^-0.5

// Scratch (allocation-free rule: device globals)
__device__ float g_qkv[M_ROWS * QKV_N];      // (n*l, 3*dim)
__device__ float g_attn_out[M_ROWS * DIM];   // (n*l, dim)

// ---------------------------------------------------------------------------
// Classic 128x128x8 register-tiled SGEMM: C = A(MxK) * B(KxN) [+ bias]
// 256 threads, 8x8 per-thread microtile. K divisible by 8, N divisible by 128.
// M guarded.
// ---------------------------------------------------------------------------
__global__ __launch_bounds__(256, 2)
void sgemm128_kernel(const float* __restrict__ A, const float* __restrict__ B,
                     const float* __restrict__ bias, float* __restrict__ C,
                     int M, int N, int K) {
    constexpr int BM = 128, BN = 128, BK = 8;
    __shared__ float As[BK][BM];
    __shared__ float Bs[BK][BN];

    const int tid  = threadIdx.x;
    const int trow = tid / 16;          // 0..15
    const int tcol = tid % 16;          // 0..15
    const int aRow = tid >> 1;          // 0..127
    const int aCol = (tid & 1) * 4;     // 0 or 4
    const int bRow = tid >> 5;          // 0..7
    const int bCol = (tid & 31) * 4;    // 0..124

    const int gARow = blockIdx.y * BM + aRow;
    const float* Bp = B + (size_t)blockIdx.x * BN;

    float acc[8][8];
#pragma unroll
    for (int m = 0; m < 8; m++)
#pragma unroll
        for (int n = 0; n < 8; n++) acc[m][n] = 0.f;

    for (int k0 = 0; k0 < K; k0 += BK) {
        float4 a4 = make_float4(0.f, 0.f, 0.f, 0.f);
        if (gARow < M)
            a4 = *(const float4*)(A + (size_t)gARow * K + k0 + aCol);
        As[aCol + 0][aRow] = a4.x;
        As[aCol + 1][aRow] = a4.y;
        As[aCol + 2][aRow] = a4.z;
        As[aCol + 3][aRow] = a4.w;

        float4 b4 = *(const float4*)(Bp + (size_t)(k0 + bRow) * N + bCol);
        *(float4*)&Bs[bRow][bCol] = b4;
        __syncthreads();

#pragma unroll
        for (int k = 0; k < BK; k++) {
            float ra[8], rb[8];
#pragma unroll
            for (int m = 0; m < 8; m++) ra[m] = As[k][trow * 8 + m];
#pragma unroll
            for (int n = 0; n < 8; n++) rb[n] = Bs[k][tcol * 8 + n];
#pragma unroll
            for (int m = 0; m < 8; m++)
#pragma unroll
                for (int n = 0; n < 8; n++)
                    acc[m][n] += ra[m] * rb[n];
        }
        __syncthreads();
    }

    const int colBase = blockIdx.x * BN + tcol * 8;
    float bv[8];
#pragma unroll
    for (int n = 0; n < 8; n++) bv[n] = bias ? bias[colBase + n] : 0.f;

#pragma unroll
    for (int m = 0; m < 8; m++) {
        int row = blockIdx.y * BM + trow * 8 + m;
        if (row < M) {
            float* Cp = C + (size_t)row * N + colBase;
            float4 v0, v1;
            v0.x = acc[m][0] + bv[0]; v0.y = acc[m][1] + bv[1];
            v0.z = acc[m][2] + bv[2]; v0.w = acc[m][3] + bv[3];
            v1.x = acc[m][4] + bv[4]; v1.y = acc[m][5] + bv[5];
            v1.z = acc[m][6] + bv[6]; v1.w = acc[m][7] + bv[7];
            *(float4*)(Cp + 0) = v0;
            *(float4*)(Cp + 4) = v1;
        }
    }
}

// ---------------------------------------------------------------------------
// Attention: one block per (window, head). K^T, V, bias-table column in smem.
// One warp per query row; full row of 343 scores in registers (11/lane).
// Mask is read as 32-bit words (nonzero == masked): correct for either an
// int32 (0/1) or float32 (0.0/1.0) widening of the original bool tensor.
// ---------------------------------------------------------------------------
__global__ __launch_bounds__(256, 2)
void attn_kernel(const float* __restrict__ qkv,
                 const float* __restrict__ table,
                 const int*   __restrict__ rel_idx,
                 const unsigned int* __restrict__ mask,
                 float* __restrict__ out) {
    extern __shared__ float smem[];
    float* Kt = smem;                       // [32][343]  Kt[c*L + m]
    float* Vs = smem + 32 * L_TOK;          // [343][32]  Vs[m*32 + c]
    float* tb = smem + 64 * L_TOK;          // [2197]

    const int w = blockIdx.x / N_HEAD;
    const int h = blockIdx.x % N_HEAD;
    const int tid  = threadIdx.x;
    const int lane = tid & 31;
    const int warp = tid >> 5;

    const float* qkvw = qkv + (size_t)w * L_TOK * QKV_N;

    for (int idx = tid; idx < L_TOK * 32; idx += 256) {
        int m = idx >> 5, c = idx & 31;
        Kt[c * L_TOK + m] = qkvw[(size_t)m * QKV_N + DIM     + h * HEAD_D + c];
        Vs[idx]           = qkvw[(size_t)m * QKV_N + 2 * DIM + h * HEAD_D + c];
    }
    for (int i = tid; i < TBL_SZ; i += 256) tb[i] = table[i * N_HEAD + h];
    __syncthreads();

    const unsigned int* mwin = mask + (size_t)w * L_TOK * L_TOK;

    for (int i = warp; i < L_TOK; i += 8) {
        // broadcast-load q row into registers (scaled)
        float q[32];
        const float* qp = qkvw + (size_t)i * QKV_N + h * HEAD_D;
#pragma unroll
        for (int c = 0; c < 32; c++) q[c] = qp[c] * SCALE_Q;

        const int* ridx = rel_idx + (size_t)i * L_TOK;
        const unsigned int* mrow = mwin + (size_t)i * L_TOK;

        float s[11];
#pragma unroll
        for (int ch = 0; ch < 11; ch++) {
            int m = ch * 32 + lane;
            float acc = -CUDART_INF_F;
            if (m < L_TOK) {
                acc = 0.f;
#pragma unroll
                for (int c = 0; c < 32; c++)
                    acc += q[c] * Kt[c * L_TOK + m];
                acc += tb[ridx[m]];
                if (mrow[m] != 0u) acc = -CUDART_INF_F;
            }
            s[ch] = acc;
        }

        // softmax over the full row (11 regs/lane + warp reduce)
        float mx = s[0];
#pragma unroll
        for (int ch = 1; ch < 11; ch++) mx = fmaxf(mx, s[ch]);
#pragma unroll
        for (int o = 16; o > 0; o >>= 1)
            mx = fmaxf(mx, __shfl_xor_sync(0xffffffffu, mx, o));
        float sum = 0.f;
#pragma unroll
        for (int ch = 0; ch < 11; ch++) {
            s[ch] = __expf(s[ch] - mx);
            sum += s[ch];
        }
#pragma unroll
        for (int o = 16; o > 0; o >>= 1)
            sum += __shfl_xor_sync(0xffffffffu, sum, o);
        const float inv = 1.f / sum;

        // out[c] = sum_m p[m] * V[m][c]; lane = channel c
        float oacc = 0.f;
#pragma unroll
        for (int ch = 0; ch < 11; ch++) {
            float p = s[ch] * inv;
            int mbase = ch * 32;
#pragma unroll
            for (int j = 0; j < 32; j++) {
                float pj = __shfl_sync(0xffffffffu, p, j);
                int m = mbase + j;
                if (m < L_TOK)
                    oacc += pj * Vs[m * 32 + lane];
            }
        }
        out[((size_t)w * L_TOK + i) * DIM + h * HEAD_D + lane] = oacc;
    }
}

// ---------------------------------------------------------------------------
extern "C" void kernel_launch(void* const* d_in, const int* in_sizes, int n_in,
                              void* d_out, int out_size) {
    const float*        x      = (const float*)d_in[0];
    const float*        qkv_w  = (const float*)d_in[1];
    const float*        table  = (const float*)d_in[2];
    const float*        proj_w = (const float*)d_in[3];
    const float*        proj_b = (const float*)d_in[4];
    const unsigned int* mask   = (const unsigned int*)d_in[5];
    const int*          relidx = (const int*)d_in[6];
    float*              out    = (float*)d_out;

    float* qkv_buf = nullptr;
    float* ao_buf  = nullptr;
    cudaGetSymbolAddress((void**)&qkv_buf, g_qkv);
    cudaGetSymbolAddress((void**)&ao_buf,  g_attn_out);

    // 1) QKV GEMM: (21952 x 384) @ (384 x 1152)
    {
        dim3 grid(QKV_N / 128, (M_ROWS + 127) / 128);
        sgemm128_kernel<<<grid, 256>>>(x, qkv_w, nullptr, qkv_buf,
                                       M_ROWS, QKV_N, DIM);
    }

    // 2) Attention per (window, head)
    {
        const int smem_bytes = (64 * L_TOK + TBL_SZ) * (int)sizeof(float); // 96596
        cudaFuncSetAttribute(attn_kernel,
                             cudaFuncAttributeMaxDynamicSharedMemorySize,
                             smem_bytes);
        attn_kernel<<<N_WIN * N_HEAD, 256, smem_bytes>>>(qkv_buf, table, relidx,
                                                         mask, ao_buf);
    }

    // 3) Projection GEMM + bias: (21952 x 384) @ (384 x 384) + b
    {
        dim3 grid(DIM / 128, (M_ROWS + 127) / 128);
        sgemm128_kernel<<<grid, 256>>>(ao_buf, proj_w, proj_b, out,
                                       M_ROWS, DIM, DIM);
    }
}

// round 6
// speedup vs baseline: 2.0931x; 2.0931x over previous
#include <cuda_runtime.h>
#include <cuda_bf16.h>
#include <cstdint>
#include <math_constants.h>

// Problem constants
#define L_TOK   343
#define N_WIN   64
#define N_HEAD  12
#define HEAD_D  32
#define DIM     384
#define QKV_N   1152
#define TBL_SZ  2197
#define M_ROWS  (N_WIN * L_TOK)          // 21952
#define SCALE_Q 0.17677669529663687f     // 32^-0.5
#define LL      (L_TOK * L_TOK)          // 117649

// Scratch (allocation-free rule: device globals)
__device__ float g_qkv[M_ROWS * QKV_N];        // (n*l, 3*dim)
__device__ float g_attn_out[M_ROWS * DIM];     // (n*l, dim)
__device__ float g_bias[N_HEAD * LL];          // bias_full[h][i][m], 5.6MB

// ---------------------------------------------------------------------------
// fp32 128x128x8 register-tiled SGEMM (unchanged from passing R1 kernel)
// ---------------------------------------------------------------------------
__global__ __launch_bounds__(256, 2)
void sgemm128_kernel(const float* __restrict__ A, const float* __restrict__ B,
                     const float* __restrict__ bias, float* __restrict__ C,
                     int M, int N, int K) {
    constexpr int BM = 128, BN = 128, BK = 8;
    __shared__ float As[BK][BM];
    __shared__ float Bs[BK][BN];

    const int tid  = threadIdx.x;
    const int trow = tid / 16;
    const int tcol = tid % 16;
    const int aRow = tid >> 1;
    const int aCol = (tid & 1) * 4;
    const int bRow = tid >> 5;
    const int bCol = (tid & 31) * 4;

    const int gARow = blockIdx.y * BM + aRow;
    const float* Bp = B + (size_t)blockIdx.x * BN;

    float acc[8][8];
#pragma unroll
    for (int m = 0; m < 8; m++)
#pragma unroll
        for (int n = 0; n < 8; n++) acc[m][n] = 0.f;

    for (int k0 = 0; k0 < K; k0 += BK) {
        float4 a4 = make_float4(0.f, 0.f, 0.f, 0.f);
        if (gARow < M)
            a4 = *(const float4*)(A + (size_t)gARow * K + k0 + aCol);
        As[aCol + 0][aRow] = a4.x;
        As[aCol + 1][aRow] = a4.y;
        As[aCol + 2][aRow] = a4.z;
        As[aCol + 3][aRow] = a4.w;

        float4 b4 = *(const float4*)(Bp + (size_t)(k0 + bRow) * N + bCol);
        *(float4*)&Bs[bRow][bCol] = b4;
        __syncthreads();

#pragma unroll
        for (int k = 0; k < BK; k++) {
            float ra[8], rb[8];
#pragma unroll
            for (int m = 0; m < 8; m++) ra[m] = As[k][trow * 8 + m];
#pragma unroll
            for (int n = 0; n < 8; n++) rb[n] = Bs[k][tcol * 8 + n];
#pragma unroll
            for (int m = 0; m < 8; m++)
#pragma unroll
                for (int n = 0; n < 8; n++)
                    acc[m][n] += ra[m] * rb[n];
        }
        __syncthreads();
    }

    const int colBase = blockIdx.x * BN + tcol * 8;
    float bv[8];
#pragma unroll
    for (int n = 0; n < 8; n++) bv[n] = bias ? bias[colBase + n] : 0.f;

#pragma unroll
    for (int m = 0; m < 8; m++) {
        int row = blockIdx.y * BM + trow * 8 + m;
        if (row < M) {
            float* Cp = C + (size_t)row * N + colBase;
            float4 v0, v1;
            v0.x = acc[m][0] + bv[0]; v0.y = acc[m][1] + bv[1];
            v0.z = acc[m][2] + bv[2]; v0.w = acc[m][3] + bv[3];
            v1.x = acc[m][4] + bv[4]; v1.y = acc[m][5] + bv[5];
            v1.z = acc[m][6] + bv[6]; v1.w = acc[m][7] + bv[7];
            *(float4*)(Cp + 0) = v0;
            *(float4*)(Cp + 4) = v1;
        }
    }
}

// ---------------------------------------------------------------------------
// Precompute bias_full[h][i][m] = table[rel_idx[i,m], h]
// ---------------------------------------------------------------------------
__global__ void bias_kernel(const float* __restrict__ table,
                            const int* __restrict__ rel_idx) {
    int tid = blockIdx.x * 256 + threadIdx.x;
    if (tid >= N_HEAD * LL) return;
    int h  = tid / LL;
    int im = tid - h * LL;
    g_bias[tid] = table[rel_idx[im] * N_HEAD + h];
}

// ---------------------------------------------------------------------------
// tf32 mma helpers
// ---------------------------------------------------------------------------
__device__ __forceinline__ uint32_t f2tf32(float f) {
    uint32_t u;
    asm("cvt.rna.tf32.f32 %0, %1;" : "=r"(u) : "f"(f));
    return u;
}

__device__ __forceinline__ void mma_tf32(float* c, const uint32_t* a, const uint32_t* b) {
    asm volatile(
        "mma.sync.aligned.m16n8k8.row.col.f32.tf32.tf32.f32 "
        "{%0,%1,%2,%3}, {%4,%5,%6,%7}, {%8,%9}, {%0,%1,%2,%3};"
        : "+f"(c[0]), "+f"(c[1]), "+f"(c[2]), "+f"(c[3])
        : "r"(a[0]), "r"(a[1]), "r"(a[2]), "r"(a[3]), "r"(b[0]), "r"(b[1]));
}

// ---------------------------------------------------------------------------
// Flash-style window attention with tf32 mma.
// Block = (q-tile of 128, head, window). 8 warps x 16 q-rows each.
// Key tiles of 64; online softmax; V rows permuted within 8-groups so the
// S C-fragments feed PV A-fragments directly (FA2 register-reuse).
// ---------------------------------------------------------------------------
#define KTILE   64
#define KSTRIDE 72   // Kts[chan][key], padded: conflict-free B-frag loads
#define VSTRIDE 40   // Vs[kpos][chan], padded: conflict-free B-frag loads

__global__ __launch_bounds__(256, 2)
void attn_mma_kernel(const float* __restrict__ qkv,
                     const unsigned int* __restrict__ mask,
                     float* __restrict__ out) {
    __shared__ float Kts[32 * KSTRIDE];   // transposed K tile (tf32 bits)
    __shared__ float Vs[KTILE * VSTRIDE]; // permuted V tile (tf32 bits)

    const int qt = blockIdx.x;   // 0..2
    const int h  = blockIdx.y;   // 0..11
    const int w  = blockIdx.z;   // 0..63
    const int tid = threadIdx.x, lane = tid & 31, wid = tid >> 5;
    const int g = lane >> 2, t = lane & 3;

    const float* qkvw = qkv + (size_t)w * L_TOK * QKV_N;
    const float* bh = g_bias + (size_t)h * LL;
    const unsigned int* mw = mask + (size_t)w * LL;

    // ---- Q fragments (built once, reused across all key tiles) ----
    const int rA = qt * 128 + wid * 16 + g;   // warp-local row g
    const int rB = rA + 8;                    // warp-local row g+8
    const int rAc = min(rA, L_TOK - 1);
    const int rBc = min(rB, L_TOK - 1);

    uint32_t qf[4][4];
#pragma unroll
    for (int kk = 0; kk < 4; kk++) {
        int c0 = h * HEAD_D + kk * 8 + t;
        float a0 = (rA < L_TOK) ? qkvw[(size_t)rA * QKV_N + c0]     * SCALE_Q : 0.f;
        float a1 = (rB < L_TOK) ? qkvw[(size_t)rB * QKV_N + c0]     * SCALE_Q : 0.f;
        float a2 = (rA < L_TOK) ? qkvw[(size_t)rA * QKV_N + c0 + 4] * SCALE_Q : 0.f;
        float a3 = (rB < L_TOK) ? qkvw[(size_t)rB * QKV_N + c0 + 4] * SCALE_Q : 0.f;
        qf[kk][0] = f2tf32(a0); qf[kk][1] = f2tf32(a1);
        qf[kk][2] = f2tf32(a2); qf[kk][3] = f2tf32(a3);
    }

    float of[4][4];
#pragma unroll
    for (int nt = 0; nt < 4; nt++)
#pragma unroll
        for (int r = 0; r < 4; r++) of[nt][r] = 0.f;

    float mA = -1e30f, mB = -1e30f, sA = 0.f, sB = 0.f;

    for (int kt = 0; kt < 6; kt++) {
        const int kb = kt * KTILE;
        __syncthreads();
        // ---- stage K (transposed) and V (row-permuted) tiles, tf32-rounded ----
        for (int idx = tid; idx < KTILE * 32; idx += 256) {
            int m = idx >> 5, c = idx & 31;
            int key = kb + m;
            float kv = (key < L_TOK) ? qkvw[(size_t)key * QKV_N + DIM     + h * HEAD_D + c] : 0.f;
            float vv = (key < L_TOK) ? qkvw[(size_t)key * QKV_N + 2 * DIM + h * HEAD_D + c] : 0.f;
            Kts[c * KSTRIDE + m] = __uint_as_float(f2tf32(kv));
            int mr = m & 7;
            int kpos = (m & ~7) | ((mr & 1) ? (mr >> 1) + 4 : (mr >> 1));
            Vs[kpos * VSTRIDE + c] = __uint_as_float(f2tf32(vv));
        }
        __syncthreads();

        // ---- S = Q * K^T (16 x 64 per warp) ----
        float sc[8][4];
#pragma unroll
        for (int j = 0; j < 8; j++)
#pragma unroll
            for (int r = 0; r < 4; r++) sc[j][r] = 0.f;

#pragma unroll
        for (int kk = 0; kk < 4; kk++) {
#pragma unroll
            for (int j = 0; j < 8; j++) {
                uint32_t b[2];
                b[0] = __float_as_uint(Kts[(kk * 8 + t)     * KSTRIDE + j * 8 + g]);
                b[1] = __float_as_uint(Kts[(kk * 8 + t + 4) * KSTRIDE + j * 8 + g]);
                mma_tf32(sc[j], qf[kk], b);
            }
        }

        // ---- bias + mask + key-padding ----
#pragma unroll
        for (int j = 0; j < 8; j++) {
            int k0 = kb + j * 8 + 2 * t;
            int k1 = k0 + 1;
            bool v0 = (k0 < L_TOK), v1 = (k1 < L_TOK);
            size_t oA = (size_t)rAc * L_TOK + k0;
            size_t oB = (size_t)rBc * L_TOK + k0;
            float bA0 = v0 ? bh[oA]     : 0.f;  unsigned mA0 = v0 ? mw[oA]     : 1u;
            float bA1 = v1 ? bh[oA + 1] : 0.f;  unsigned mA1 = v1 ? mw[oA + 1] : 1u;
            float bB0 = v0 ? bh[oB]     : 0.f;  unsigned mB0 = v0 ? mw[oB]     : 1u;
            float bB1 = v1 ? bh[oB + 1] : 0.f;  unsigned mB1 = v1 ? mw[oB + 1] : 1u;
            sc[j][0] = mA0 ? -1e30f : sc[j][0] + bA0;
            sc[j][1] = mA1 ? -1e30f : sc[j][1] + bA1;
            sc[j][2] = mB0 ? -1e30f : sc[j][2] + bB0;
            sc[j][3] = mB1 ? -1e30f : sc[j][3] + bB1;
        }

        // ---- online softmax (rows rA, rB; quad = lanes sharing g) ----
        float tmA = -1e30f, tmB = -1e30f;
#pragma unroll
        for (int j = 0; j < 8; j++) {
            tmA = fmaxf(tmA, fmaxf(sc[j][0], sc[j][1]));
            tmB = fmaxf(tmB, fmaxf(sc[j][2], sc[j][3]));
        }
        tmA = fmaxf(tmA, __shfl_xor_sync(0xffffffffu, tmA, 1));
        tmA = fmaxf(tmA, __shfl_xor_sync(0xffffffffu, tmA, 2));
        tmB = fmaxf(tmB, __shfl_xor_sync(0xffffffffu, tmB, 1));
        tmB = fmaxf(tmB, __shfl_xor_sync(0xffffffffu, tmB, 2));

        float mAn = fmaxf(mA, tmA), mBn = fmaxf(mB, tmB);
        float fA = __expf(mA - mAn), fB = __expf(mB - mBn);
        mA = mAn; mB = mBn;

        float tsA = 0.f, tsB = 0.f;
#pragma unroll
        for (int j = 0; j < 8; j++) {
            sc[j][0] = __expf(sc[j][0] - mAn);
            sc[j][1] = __expf(sc[j][1] - mAn);
            sc[j][2] = __expf(sc[j][2] - mBn);
            sc[j][3] = __expf(sc[j][3] - mBn);
            tsA += sc[j][0] + sc[j][1];
            tsB += sc[j][2] + sc[j][3];
        }
        tsA += __shfl_xor_sync(0xffffffffu, tsA, 1);
        tsA += __shfl_xor_sync(0xffffffffu, tsA, 2);
        tsB += __shfl_xor_sync(0xffffffffu, tsB, 1);
        tsB += __shfl_xor_sync(0xffffffffu, tsB, 2);
        sA = sA * fA + tsA;
        sB = sB * fB + tsB;

#pragma unroll
        for (int nt = 0; nt < 4; nt++) {
            of[nt][0] *= fA; of[nt][1] *= fA;
            of[nt][2] *= fB; of[nt][3] *= fB;
        }

        // ---- O += P * V (P = S C-frags reused as A-frags via V row perm) ----
#pragma unroll
        for (int j = 0; j < 8; j++) {
            uint32_t a[4];
            a[0] = f2tf32(sc[j][0]);
            a[1] = f2tf32(sc[j][2]);
            a[2] = f2tf32(sc[j][1]);
            a[3] = f2tf32(sc[j][3]);
#pragma unroll
            for (int nt = 0; nt < 4; nt++) {
                uint32_t b[2];
                b[0] = __float_as_uint(Vs[(j * 8 + t)     * VSTRIDE + nt * 8 + g]);
                b[1] = __float_as_uint(Vs[(j * 8 + t + 4) * VSTRIDE + nt * 8 + g]);
                mma_tf32(of[nt], a, b);
            }
        }
    }

    // ---- epilogue ----
    float iA = 1.f / sA, iB = 1.f / sB;
    if (rA < L_TOK) {
        float* op = out + ((size_t)(w * L_TOK + rA)) * DIM + h * HEAD_D;
#pragma unroll
        for (int nt = 0; nt < 4; nt++) {
            float2 v = make_float2(of[nt][0] * iA, of[nt][1] * iA);
            *(float2*)(op + nt * 8 + 2 * t) = v;
        }
    }
    if (rB < L_TOK) {
        float* op = out + ((size_t)(w * L_TOK + rB)) * DIM + h * HEAD_D;
#pragma unroll
        for (int nt = 0; nt < 4; nt++) {
            float2 v = make_float2(of[nt][2] * iB, of[nt][3] * iB);
            *(float2*)(op + nt * 8 + 2 * t) = v;
        }
    }
}

// ---------------------------------------------------------------------------
extern "C" void kernel_launch(void* const* d_in, const int* in_sizes, int n_in,
                              void* d_out, int out_size) {
    const float*        x      = (const float*)d_in[0];
    const float*        qkv_w  = (const float*)d_in[1];
    const float*        table  = (const float*)d_in[2];
    const float*        proj_w = (const float*)d_in[3];
    const float*        proj_b = (const float*)d_in[4];
    const unsigned int* mask   = (const unsigned int*)d_in[5];
    const int*          relidx = (const int*)d_in[6];
    float*              out    = (float*)d_out;

    float* qkv_buf = nullptr;
    float* ao_buf  = nullptr;
    cudaGetSymbolAddress((void**)&qkv_buf, g_qkv);
    cudaGetSymbolAddress((void**)&ao_buf,  g_attn_out);

    // 0) bias_full precompute (independent of QKV GEMM)
    {
        int total = N_HEAD * LL;
        bias_kernel<<<(total + 255) / 256, 256>>>(table, relidx);
    }

    // 1) QKV GEMM: (21952 x 384) @ (384 x 1152), fp32
    {
        dim3 grid(QKV_N / 128, (M_ROWS + 127) / 128);
        sgemm128_kernel<<<grid, 256>>>(x, qkv_w, nullptr, qkv_buf,
                                       M_ROWS, QKV_N, DIM);
    }

    // 2) Attention: tf32 mma flash-style
    {
        dim3 grid(3, N_HEAD, N_WIN);
        attn_mma_kernel<<<grid, 256>>>(qkv_buf, mask, ao_buf);
    }

    // 3) Projection GEMM + bias: (21952 x 384) @ (384 x 384) + b, fp32
    {
        dim3 grid(DIM / 128, (M_ROWS + 127) / 128);
        sgemm128_kernel<<<grid, 256>>>(ao_buf, proj_w, proj_b, out,
                                       M_ROWS, DIM, DIM);
    }
}

// round 8
// speedup vs baseline: 3.3457x; 1.5985x over previous
#include <cuda_runtime.h>
#include <cuda_bf16.h>
#include <cstdint>
#include <math_constants.h>

// Problem constants
#define L_TOK   343
#define N_WIN   64
#define N_HEAD  12
#define HEAD_D  32
#define DIM     384
#define QKV_N   1152
#define TBL_SZ  2197
#define M_ROWS  (N_WIN * L_TOK)          // 21952
#define SCALE_Q 0.17677669529663687f     // 32^-0.5
#define LL      (L_TOK * L_TOK)          // 117649

// Scratch (allocation-free rule: device globals)
__device__ float g_qkv[M_ROWS * QKV_N];        // (n*l, 3*dim)
__device__ float g_attn_out[M_ROWS * DIM];     // (n*l, dim)
__device__ float g_bias[N_HEAD * LL];          // bias_full[h][i][m], 5.6MB

// ---------------------------------------------------------------------------
// tf32 mma helpers
// ---------------------------------------------------------------------------
__device__ __forceinline__ uint32_t f2tf32(float f) {
    uint32_t u;
    asm("cvt.rna.tf32.f32 %0, %1;" : "=r"(u) : "f"(f));
    return u;
}

__device__ __forceinline__ void mma_tf32(float* c, const uint32_t* a, const uint32_t* b) {
    asm volatile(
        "mma.sync.aligned.m16n8k8.row.col.f32.tf32.tf32.f32 "
        "{%0,%1,%2,%3}, {%4,%5,%6,%7}, {%8,%9}, {%0,%1,%2,%3};"
        : "+f"(c[0]), "+f"(c[1]), "+f"(c[2]), "+f"(c[3])
        : "r"(a[0]), "r"(a[1]), "r"(a[2]), "r"(a[3]), "r"(b[0]), "r"(b[1]));
}

// ---------------------------------------------------------------------------
// tf32 tensor-core GEMM: C = A(MxK) * B(KxN) [+ bias]
// Block 128x128xBK32, 8 warps (4m x 2n), warp tile 32x64.
// As[m][k] stride 36  -> A-frag LDS bank = 4g+t (conflict-free)
// Bs[k][n] stride 132 -> B-frag LDS bank = 4t+g (conflict-free)
// Double-buffered smem; tf32 rounding at staging.
// Requires: K % 32 == 0, N % 128 == 0. M guarded.
// ---------------------------------------------------------------------------
#define G_BM 128
#define G_BN 128
#define G_BK 32
#define G_AS 36
#define G_BS 132
#define G_SMEM_STAGE (G_BM * G_AS + G_BK * G_BS)          // 8832 floats
#define G_SMEM_BYTES (2 * G_SMEM_STAGE * 4)               // 70656 bytes

__global__ __launch_bounds__(256, 2)
void tf32_gemm_kernel(const float* __restrict__ A, const float* __restrict__ B,
                      const float* __restrict__ bias, float* __restrict__ C,
                      int M, int N, int K) {
    extern __shared__ float sm[];
    float* Abuf[2] = { sm,                 sm + G_SMEM_STAGE };
    float* Bbuf[2] = { sm + G_BM * G_AS,   sm + G_SMEM_STAGE + G_BM * G_AS };

    const int tid  = threadIdx.x;
    const int lane = tid & 31;
    const int wid  = tid >> 5;
    const int g = lane >> 2, t = lane & 3;

    const int m0w = (wid & 3) * 32;   // warp m-offset in block tile
    const int n0w = (wid >> 2) * 64;  // warp n-offset in block tile

    const int bm0 = blockIdx.y * G_BM;
    const int bn0 = blockIdx.x * G_BN;

    const int arow = tid >> 3;          // 0..31 (A: +r*32)
    const int acol = (tid & 7) << 2;    // 0..28
    const int brow = tid >> 5;          // 0..7  (B: +r*8)
    const int bcol = (tid & 31) << 2;   // 0..124

    float4 av[4], bv[4];

    // ---- prologue: load k-tile 0 ----
#pragma unroll
    for (int r = 0; r < 4; r++) {
        int row = bm0 + r * 32 + arow;
        av[r] = (row < M) ? *(const float4*)(A + (size_t)row * K + acol)
                          : make_float4(0.f, 0.f, 0.f, 0.f);
        bv[r] = *(const float4*)(B + (size_t)(r * 8 + brow) * N + bn0 + bcol);
    }
#pragma unroll
    for (int r = 0; r < 4; r++) {
        float4 ac = make_float4(__uint_as_float(f2tf32(av[r].x)), __uint_as_float(f2tf32(av[r].y)),
                                __uint_as_float(f2tf32(av[r].z)), __uint_as_float(f2tf32(av[r].w)));
        *(float4*)&Abuf[0][(r * 32 + arow) * G_AS + acol] = ac;
        float4 bc = make_float4(__uint_as_float(f2tf32(bv[r].x)), __uint_as_float(f2tf32(bv[r].y)),
                                __uint_as_float(f2tf32(bv[r].z)), __uint_as_float(f2tf32(bv[r].w)));
        *(float4*)&Bbuf[0][(r * 8 + brow) * G_BS + bcol] = bc;
    }
    __syncthreads();

    float c[2][8][4];
#pragma unroll
    for (int mt = 0; mt < 2; mt++)
#pragma unroll
        for (int nt = 0; nt < 8; nt++)
#pragma unroll
            for (int r = 0; r < 4; r++) c[mt][nt][r] = 0.f;

    const int nk = K / G_BK;   // 12
    for (int kt = 0; kt < nk; kt++) {
        const int cur = kt & 1, nxt = cur ^ 1;

        // issue global loads for next tile
        if (kt + 1 < nk) {
            const int k0 = (kt + 1) * G_BK;
#pragma unroll
            for (int r = 0; r < 4; r++) {
                int row = bm0 + r * 32 + arow;
                av[r] = (row < M) ? *(const float4*)(A + (size_t)row * K + k0 + acol)
                                  : make_float4(0.f, 0.f, 0.f, 0.f);
                bv[r] = *(const float4*)(B + (size_t)(k0 + r * 8 + brow) * N + bn0 + bcol);
            }
        }

        // compute on current buffer
        const float* Asb = Abuf[cur];
        const float* Bsb = Bbuf[cur];
#pragma unroll
        for (int kk = 0; kk < 4; kk++) {
            const int k8 = kk * 8;
            uint32_t a[2][4], b[8][2];
#pragma unroll
            for (int mt = 0; mt < 2; mt++) {
                int m0 = m0w + mt * 16;
                a[mt][0] = __float_as_uint(Asb[(m0 + g)     * G_AS + k8 + t]);
                a[mt][1] = __float_as_uint(Asb[(m0 + g + 8) * G_AS + k8 + t]);
                a[mt][2] = __float_as_uint(Asb[(m0 + g)     * G_AS + k8 + t + 4]);
                a[mt][3] = __float_as_uint(Asb[(m0 + g + 8) * G_AS + k8 + t + 4]);
            }
#pragma unroll
            for (int nt = 0; nt < 8; nt++) {
                int n0 = n0w + nt * 8;
                b[nt][0] = __float_as_uint(Bsb[(k8 + t)     * G_BS + n0 + g]);
                b[nt][1] = __float_as_uint(Bsb[(k8 + t + 4) * G_BS + n0 + g]);
            }
#pragma unroll
            for (int mt = 0; mt < 2; mt++)
#pragma unroll
                for (int nt = 0; nt < 8; nt++)
                    mma_tf32(c[mt][nt], a[mt], b[nt]);
        }

        // stage next tile
        if (kt + 1 < nk) {
#pragma unroll
            for (int r = 0; r < 4; r++) {
                float4 ac = make_float4(__uint_as_float(f2tf32(av[r].x)), __uint_as_float(f2tf32(av[r].y)),
                                        __uint_as_float(f2tf32(av[r].z)), __uint_as_float(f2tf32(av[r].w)));
                *(float4*)&Abuf[nxt][(r * 32 + arow) * G_AS + acol] = ac;
                float4 bc = make_float4(__uint_as_float(f2tf32(bv[r].x)), __uint_as_float(f2tf32(bv[r].y)),
                                        __uint_as_float(f2tf32(bv[r].z)), __uint_as_float(f2tf32(bv[r].w)));
                *(float4*)&Bbuf[nxt][(r * 8 + brow) * G_BS + bcol] = bc;
            }
        }
        __syncthreads();
    }

    // ---- epilogue: bias + store ----
#pragma unroll
    for (int mt = 0; mt < 2; mt++) {
        int row0 = bm0 + m0w + mt * 16 + g;
#pragma unroll
        for (int nt = 0; nt < 8; nt++) {
            int col = bn0 + n0w + nt * 8 + 2 * t;
            float b0 = 0.f, b1 = 0.f;
            if (bias) { b0 = bias[col]; b1 = bias[col + 1]; }
            if (row0 < M)
                *(float2*)(C + (size_t)row0 * N + col) =
                    make_float2(c[mt][nt][0] + b0, c[mt][nt][1] + b1);
            if (row0 + 8 < M)
                *(float2*)(C + (size_t)(row0 + 8) * N + col) =
                    make_float2(c[mt][nt][2] + b0, c[mt][nt][3] + b1);
        }
    }
}

// ---------------------------------------------------------------------------
// Precompute bias_full[h][i][m] = table[rel_idx[i,m], h]
// ---------------------------------------------------------------------------
__global__ void bias_kernel(const float* __restrict__ table,
                            const int* __restrict__ rel_idx) {
    int tid = blockIdx.x * 256 + threadIdx.x;
    if (tid >= N_HEAD * LL) return;
    int h  = tid / LL;
    int im = tid - h * LL;
    g_bias[tid] = table[rel_idx[im] * N_HEAD + h];
}

// ---------------------------------------------------------------------------
// Flash-style window attention with tf32 mma (unchanged from R6 pass).
// ---------------------------------------------------------------------------
#define KTILE   64
#define KSTRIDE 72
#define VSTRIDE 40

__global__ __launch_bounds__(256, 2)
void attn_mma_kernel(const float* __restrict__ qkv,
                     const unsigned int* __restrict__ mask,
                     float* __restrict__ out) {
    __shared__ float Kts[32 * KSTRIDE];
    __shared__ float Vs[KTILE * VSTRIDE];

    const int qt = blockIdx.x;
    const int h  = blockIdx.y;
    const int w  = blockIdx.z;
    const int tid = threadIdx.x, lane = tid & 31, wid = tid >> 5;
    const int g = lane >> 2, t = lane & 3;

    const float* qkvw = qkv + (size_t)w * L_TOK * QKV_N;
    const float* bh = g_bias + (size_t)h * LL;
    const unsigned int* mw = mask + (size_t)w * LL;

    const int rA = qt * 128 + wid * 16 + g;
    const int rB = rA + 8;
    const int rAc = min(rA, L_TOK - 1);
    const int rBc = min(rB, L_TOK - 1);

    uint32_t qf[4][4];
#pragma unroll
    for (int kk = 0; kk < 4; kk++) {
        int c0 = h * HEAD_D + kk * 8 + t;
        float a0 = (rA < L_TOK) ? qkvw[(size_t)rA * QKV_N + c0]     * SCALE_Q : 0.f;
        float a1 = (rB < L_TOK) ? qkvw[(size_t)rB * QKV_N + c0]     * SCALE_Q : 0.f;
        float a2 = (rA < L_TOK) ? qkvw[(size_t)rA * QKV_N + c0 + 4] * SCALE_Q : 0.f;
        float a3 = (rB < L_TOK) ? qkvw[(size_t)rB * QKV_N + c0 + 4] * SCALE_Q : 0.f;
        qf[kk][0] = f2tf32(a0); qf[kk][1] = f2tf32(a1);
        qf[kk][2] = f2tf32(a2); qf[kk][3] = f2tf32(a3);
    }

    float of[4][4];
#pragma unroll
    for (int nt = 0; nt < 4; nt++)
#pragma unroll
        for (int r = 0; r < 4; r++) of[nt][r] = 0.f;

    float mA = -1e30f, mB = -1e30f, sA = 0.f, sB = 0.f;

    for (int kt = 0; kt < 6; kt++) {
        const int kb = kt * KTILE;
        __syncthreads();
        for (int idx = tid; idx < KTILE * 32; idx += 256) {
            int m = idx >> 5, c = idx & 31;
            int key = kb + m;
            float kv = (key < L_TOK) ? qkvw[(size_t)key * QKV_N + DIM     + h * HEAD_D + c] : 0.f;
            float vv = (key < L_TOK) ? qkvw[(size_t)key * QKV_N + 2 * DIM + h * HEAD_D + c] : 0.f;
            Kts[c * KSTRIDE + m] = __uint_as_float(f2tf32(kv));
            int mr = m & 7;
            int kpos = (m & ~7) | ((mr & 1) ? (mr >> 1) + 4 : (mr >> 1));
            Vs[kpos * VSTRIDE + c] = __uint_as_float(f2tf32(vv));
        }
        __syncthreads();

        float sc[8][4];
#pragma unroll
        for (int j = 0; j < 8; j++)
#pragma unroll
            for (int r = 0; r < 4; r++) sc[j][r] = 0.f;

#pragma unroll
        for (int kk = 0; kk < 4; kk++) {
#pragma unroll
            for (int j = 0; j < 8; j++) {
                uint32_t b[2];
                b[0] = __float_as_uint(Kts[(kk * 8 + t)     * KSTRIDE + j * 8 + g]);
                b[1] = __float_as_uint(Kts[(kk * 8 + t + 4) * KSTRIDE + j * 8 + g]);
                mma_tf32(sc[j], qf[kk], b);
            }
        }

#pragma unroll
        for (int j = 0; j < 8; j++) {
            int k0 = kb + j * 8 + 2 * t;
            int k1 = k0 + 1;
            bool v0 = (k0 < L_TOK), v1 = (k1 < L_TOK);
            size_t oA = (size_t)rAc * L_TOK + k0;
            size_t oB = (size_t)rBc * L_TOK + k0;
            float bA0 = v0 ? bh[oA]     : 0.f;  unsigned mA0 = v0 ? mw[oA]     : 1u;
            float bA1 = v1 ? bh[oA + 1] : 0.f;  unsigned mA1 = v1 ? mw[oA + 1] : 1u;
            float bB0 = v0 ? bh[oB]     : 0.f;  unsigned mB0 = v0 ? mw[oB]     : 1u;
            float bB1 = v1 ? bh[oB + 1] : 0.f;  unsigned mB1 = v1 ? mw[oB + 1] : 1u;
            sc[j][0] = mA0 ? -1e30f : sc[j][0] + bA0;
            sc[j][1] = mA1 ? -1e30f : sc[j][1] + bA1;
            sc[j][2] = mB0 ? -1e30f : sc[j][2] + bB0;
            sc[j][3] = mB1 ? -1e30f : sc[j][3] + bB1;
        }

        float tmA = -1e30f, tmB = -1e30f;
#pragma unroll
        for (int j = 0; j < 8; j++) {
            tmA = fmaxf(tmA, fmaxf(sc[j][0], sc[j][1]));
            tmB = fmaxf(tmB, fmaxf(sc[j][2], sc[j][3]));
        }
        tmA = fmaxf(tmA, __shfl_xor_sync(0xffffffffu, tmA, 1));
        tmA = fmaxf(tmA, __shfl_xor_sync(0xffffffffu, tmA, 2));
        tmB = fmaxf(tmB, __shfl_xor_sync(0xffffffffu, tmB, 1));
        tmB = fmaxf(tmB, __shfl_xor_sync(0xffffffffu, tmB, 2));

        float mAn = fmaxf(mA, tmA), mBn = fmaxf(mB, tmB);
        float fA = __expf(mA - mAn), fB = __expf(mB - mBn);
        mA = mAn; mB = mBn;

        float tsA = 0.f, tsB = 0.f;
#pragma unroll
        for (int j = 0; j < 8; j++) {
            sc[j][0] = __expf(sc[j][0] - mAn);
            sc[j][1] = __expf(sc[j][1] - mAn);
            sc[j][2] = __expf(sc[j][2] - mBn);
            sc[j][3] = __expf(sc[j][3] - mBn);
            tsA += sc[j][0] + sc[j][1];
            tsB += sc[j][2] + sc[j][3];
        }
        tsA += __shfl_xor_sync(0xffffffffu, tsA, 1);
        tsA += __shfl_xor_sync(0xffffffffu, tsA, 2);
        tsB += __shfl_xor_sync(0xffffffffu, tsB, 1);
        tsB += __shfl_xor_sync(0xffffffffu, tsB, 2);
        sA = sA * fA + tsA;
        sB = sB * fB + tsB;

#pragma unroll
        for (int nt = 0; nt < 4; nt++) {
            of[nt][0] *= fA; of[nt][1] *= fA;
            of[nt][2] *= fB; of[nt][3] *= fB;
        }

#pragma unroll
        for (int j = 0; j < 8; j++) {
            uint32_t a[4];
            a[0] = f2tf32(sc[j][0]);
            a[1] = f2tf32(sc[j][2]);
            a[2] = f2tf32(sc[j][1]);
            a[3] = f2tf32(sc[j][3]);
#pragma unroll
            for (int nt = 0; nt < 4; nt++) {
                uint32_t b[2];
                b[0] = __float_as_uint(Vs[(j * 8 + t)     * VSTRIDE + nt * 8 + g]);
                b[1] = __float_as_uint(Vs[(j * 8 + t + 4) * VSTRIDE + nt * 8 + g]);
                mma_tf32(of[nt], a, b);
            }
        }
    }

    float iA = 1.f / sA, iB = 1.f / sB;
    if (rA < L_TOK) {
        float* op = out + ((size_t)(w * L_TOK + rA)) * DIM + h * HEAD_D;
#pragma unroll
        for (int nt = 0; nt < 4; nt++) {
            float2 v = make_float2(of[nt][0] * iA, of[nt][1] * iA);
            *(float2*)(op + nt * 8 + 2 * t) = v;
        }
    }
    if (rB < L_TOK) {
        float* op = out + ((size_t)(w * L_TOK + rB)) * DIM + h * HEAD_D;
#pragma unroll
        for (int nt = 0; nt < 4; nt++) {
            float2 v = make_float2(of[nt][2] * iB, of[nt][3] * iB);
            *(float2*)(op + nt * 8 + 2 * t) = v;
        }
    }
}

// ---------------------------------------------------------------------------
extern "C" void kernel_launch(void* const* d_in, const int* in_sizes, int n_in,
                              void* d_out, int out_size) {
    const float*        x      = (const float*)d_in[0];
    const float*        qkv_w  = (const float*)d_in[1];
    const float*        table  = (const float*)d_in[2];
    const float*        proj_w = (const float*)d_in[3];
    const float*        proj_b = (const float*)d_in[4];
    const unsigned int* mask   = (const unsigned int*)d_in[5];
    const int*          relidx = (const int*)d_in[6];
    float*              out    = (float*)d_out;

    float* qkv_buf = nullptr;
    float* ao_buf  = nullptr;
    cudaGetSymbolAddress((void**)&qkv_buf, g_qkv);
    cudaGetSymbolAddress((void**)&ao_buf,  g_attn_out);

    cudaFuncSetAttribute(tf32_gemm_kernel,
                         cudaFuncAttributeMaxDynamicSharedMemorySize,
                         G_SMEM_BYTES);

    // 0) bias_full precompute
    {
        int total = N_HEAD * LL;
        bias_kernel<<<(total + 255) / 256, 256>>>(table, relidx);
    }

    // 1) QKV GEMM: (21952 x 384) @ (384 x 1152), tf32 tensor cores
    {
        dim3 grid(QKV_N / G_BN, (M_ROWS + G_BM - 1) / G_BM);
        tf32_gemm_kernel<<<grid, 256, G_SMEM_BYTES>>>(x, qkv_w, nullptr, qkv_buf,
                                                      M_ROWS, QKV_N, DIM);
    }

    // 2) Attention: tf32 mma flash-style
    {
        dim3 grid(3, N_HEAD, N_WIN);
        attn_mma_kernel<<<grid, 256>>>(qkv_buf, mask, ao_buf);
    }

    // 3) Projection GEMM + bias: (21952 x 384) @ (384 x 384) + b, tf32
    {
        dim3 grid(DIM / G_BN, (M_ROWS + G_BM - 1) / G_BM);
        tf32_gemm_kernel<<<grid, 256, G_SMEM_BYTES>>>(ao_buf, proj_w, proj_b, out,
                                                      M_ROWS, DIM, DIM);
    }
}

// round 9
// speedup vs baseline: 4.7776x; 1.4280x over previous
#include <cuda_runtime.h>
#include <cuda_bf16.h>
#include <cstdint>
#include <math_constants.h>

// Problem constants
#define L_TOK   343
#define N_WIN   64
#define N_HEAD  12
#define HEAD_D  32
#define DIM     384
#define QKV_N   1152
#define TBL_SZ  2197
#define M_ROWS  (N_WIN * L_TOK)          // 21952
#define SCALE_Q 0.17677669529663687f     // 32^-0.5
#define LOG2E_F 1.4426950408889634f
#define LL      (L_TOK * L_TOK)          // 117649
#define B_STR   384                      // padded bias row stride
#define MW_STR  12                       // mask words per row (343 bits -> 12 words padded)

// Scratch (allocation-free rule: device globals)
__device__ float    g_qkv[M_ROWS * QKV_N];           // (n*l, 3*dim)
__device__ float    g_attn_out[M_ROWS * DIM];        // (n*l, dim)
__device__ float    g_bias[N_HEAD * L_TOK * B_STR];  // bias*log2e, padded, 6.3MB
__device__ uint32_t g_mbits[N_WIN * L_TOK * MW_STR]; // packed mask bits, 1.05MB

// ---------------------------------------------------------------------------
// tf32 mma helpers
// ---------------------------------------------------------------------------
__device__ __forceinline__ uint32_t f2tf32(float f) {
    uint32_t u;
    asm("cvt.rna.tf32.f32 %0, %1;" : "=r"(u) : "f"(f));
    return u;
}

__device__ __forceinline__ void mma_tf32(float* c, const uint32_t* a, const uint32_t* b) {
    asm volatile(
        "mma.sync.aligned.m16n8k8.row.col.f32.tf32.tf32.f32 "
        "{%0,%1,%2,%3}, {%4,%5,%6,%7}, {%8,%9}, {%0,%1,%2,%3};"
        : "+f"(c[0]), "+f"(c[1]), "+f"(c[2]), "+f"(c[3])
        : "r"(a[0]), "r"(a[1]), "r"(a[2]), "r"(a[3]), "r"(b[0]), "r"(b[1]));
}

__device__ __forceinline__ float ex2f(float x) {
    float r;
    asm("ex2.approx.f32 %0, %1;" : "=f"(r) : "f"(x));
    return r;
}

// ---------------------------------------------------------------------------
// tf32 tensor-core GEMM (unchanged from R8 pass)
// ---------------------------------------------------------------------------
#define G_BM 128
#define G_BN 128
#define G_BK 32
#define G_AS 36
#define G_BS 132
#define G_SMEM_STAGE (G_BM * G_AS + G_BK * G_BS)
#define G_SMEM_BYTES (2 * G_SMEM_STAGE * 4)

__global__ __launch_bounds__(256, 2)
void tf32_gemm_kernel(const float* __restrict__ A, const float* __restrict__ B,
                      const float* __restrict__ bias, float* __restrict__ C,
                      int M, int N, int K) {
    extern __shared__ float sm[];
    float* Abuf[2] = { sm,                 sm + G_SMEM_STAGE };
    float* Bbuf[2] = { sm + G_BM * G_AS,   sm + G_SMEM_STAGE + G_BM * G_AS };

    const int tid  = threadIdx.x;
    const int lane = tid & 31;
    const int wid  = tid >> 5;
    const int g = lane >> 2, t = lane & 3;

    const int m0w = (wid & 3) * 32;
    const int n0w = (wid >> 2) * 64;

    const int bm0 = blockIdx.y * G_BM;
    const int bn0 = blockIdx.x * G_BN;

    const int arow = tid >> 3;
    const int acol = (tid & 7) << 2;
    const int brow = tid >> 5;
    const int bcol = (tid & 31) << 2;

    float4 av[4], bv[4];

#pragma unroll
    for (int r = 0; r < 4; r++) {
        int row = bm0 + r * 32 + arow;
        av[r] = (row < M) ? *(const float4*)(A + (size_t)row * K + acol)
                          : make_float4(0.f, 0.f, 0.f, 0.f);
        bv[r] = *(const float4*)(B + (size_t)(r * 8 + brow) * N + bn0 + bcol);
    }
#pragma unroll
    for (int r = 0; r < 4; r++) {
        float4 ac = make_float4(__uint_as_float(f2tf32(av[r].x)), __uint_as_float(f2tf32(av[r].y)),
                                __uint_as_float(f2tf32(av[r].z)), __uint_as_float(f2tf32(av[r].w)));
        *(float4*)&Abuf[0][(r * 32 + arow) * G_AS + acol] = ac;
        float4 bc = make_float4(__uint_as_float(f2tf32(bv[r].x)), __uint_as_float(f2tf32(bv[r].y)),
                                __uint_as_float(f2tf32(bv[r].z)), __uint_as_float(f2tf32(bv[r].w)));
        *(float4*)&Bbuf[0][(r * 8 + brow) * G_BS + bcol] = bc;
    }
    __syncthreads();

    float c[2][8][4];
#pragma unroll
    for (int mt = 0; mt < 2; mt++)
#pragma unroll
        for (int nt = 0; nt < 8; nt++)
#pragma unroll
            for (int r = 0; r < 4; r++) c[mt][nt][r] = 0.f;

    const int nk = K / G_BK;
    for (int kt = 0; kt < nk; kt++) {
        const int cur = kt & 1, nxt = cur ^ 1;

        if (kt + 1 < nk) {
            const int k0 = (kt + 1) * G_BK;
#pragma unroll
            for (int r = 0; r < 4; r++) {
                int row = bm0 + r * 32 + arow;
                av[r] = (row < M) ? *(const float4*)(A + (size_t)row * K + k0 + acol)
                                  : make_float4(0.f, 0.f, 0.f, 0.f);
                bv[r] = *(const float4*)(B + (size_t)(k0 + r * 8 + brow) * N + bn0 + bcol);
            }
        }

        const float* Asb = Abuf[cur];
        const float* Bsb = Bbuf[cur];
#pragma unroll
        for (int kk = 0; kk < 4; kk++) {
            const int k8 = kk * 8;
            uint32_t a[2][4], b[8][2];
#pragma unroll
            for (int mt = 0; mt < 2; mt++) {
                int m0 = m0w + mt * 16;
                a[mt][0] = __float_as_uint(Asb[(m0 + g)     * G_AS + k8 + t]);
                a[mt][1] = __float_as_uint(Asb[(m0 + g + 8) * G_AS + k8 + t]);
                a[mt][2] = __float_as_uint(Asb[(m0 + g)     * G_AS + k8 + t + 4]);
                a[mt][3] = __float_as_uint(Asb[(m0 + g + 8) * G_AS + k8 + t + 4]);
            }
#pragma unroll
            for (int nt = 0; nt < 8; nt++) {
                int n0 = n0w + nt * 8;
                b[nt][0] = __float_as_uint(Bsb[(k8 + t)     * G_BS + n0 + g]);
                b[nt][1] = __float_as_uint(Bsb[(k8 + t + 4) * G_BS + n0 + g]);
            }
#pragma unroll
            for (int mt = 0; mt < 2; mt++)
#pragma unroll
                for (int nt = 0; nt < 8; nt++)
                    mma_tf32(c[mt][nt], a[mt], b[nt]);
        }

        if (kt + 1 < nk) {
#pragma unroll
            for (int r = 0; r < 4; r++) {
                float4 ac = make_float4(__uint_as_float(f2tf32(av[r].x)), __uint_as_float(f2tf32(av[r].y)),
                                        __uint_as_float(f2tf32(av[r].z)), __uint_as_float(f2tf32(av[r].w)));
                *(float4*)&Abuf[nxt][(r * 32 + arow) * G_AS + acol] = ac;
                float4 bc = make_float4(__uint_as_float(f2tf32(bv[r].x)), __uint_as_float(f2tf32(bv[r].y)),
                                        __uint_as_float(f2tf32(bv[r].z)), __uint_as_float(f2tf32(bv[r].w)));
                *(float4*)&Bbuf[nxt][(r * 8 + brow) * G_BS + bcol] = bc;
            }
        }
        __syncthreads();
    }

#pragma unroll
    for (int mt = 0; mt < 2; mt++) {
        int row0 = bm0 + m0w + mt * 16 + g;
#pragma unroll
        for (int nt = 0; nt < 8; nt++) {
            int col = bn0 + n0w + nt * 8 + 2 * t;
            float b0 = 0.f, b1 = 0.f;
            if (bias) { b0 = bias[col]; b1 = bias[col + 1]; }
            if (row0 < M)
                *(float2*)(C + (size_t)row0 * N + col) =
                    make_float2(c[mt][nt][0] + b0, c[mt][nt][1] + b1);
            if (row0 + 8 < M)
                *(float2*)(C + (size_t)(row0 + 8) * N + col) =
                    make_float2(c[mt][nt][2] + b0, c[mt][nt][3] + b1);
        }
    }
}

// ---------------------------------------------------------------------------
// Precompute padded bias (x log2e): g_bias[h][i][m], m in [0,384), 0 past 343
// ---------------------------------------------------------------------------
__global__ void bias_kernel(const float* __restrict__ table,
                            const int* __restrict__ rel_idx) {
    int tid = blockIdx.x * 256 + threadIdx.x;
    if (tid >= N_HEAD * L_TOK * B_STR) return;
    int h  = tid / (L_TOK * B_STR);
    int rm = tid - h * (L_TOK * B_STR);
    int i  = rm / B_STR;
    int m  = rm - i * B_STR;
    float v = 0.f;
    if (m < L_TOK)
        v = table[rel_idx[i * L_TOK + m] * N_HEAD + h] * LOG2E_F;
    g_bias[tid] = v;
}

// ---------------------------------------------------------------------------
// Pack mask into bits: one warp per (w,i) row; ballot over 32 keys per word.
// Keys >= 343 are marked masked (bit=1).
// ---------------------------------------------------------------------------
__global__ void maskpack_kernel(const unsigned int* __restrict__ mask) {
    int row = blockIdx.x * (blockDim.x >> 5) + (threadIdx.x >> 5); // (w*343+i)
    int lane = threadIdx.x & 31;
    if (row >= N_WIN * L_TOK) return;
    const unsigned int* mrow = mask + (size_t)row * L_TOK;
#pragma unroll
    for (int wd = 0; wd < MW_STR; wd++) {
        int key = wd * 32 + lane;
        int bit = (key < L_TOK) ? (mrow[key] != 0u) : 1;
        unsigned int word = __ballot_sync(0xffffffffu, bit);
        if (lane == 0) g_mbits[(size_t)row * MW_STR + wd] = word;
    }
}

// ---------------------------------------------------------------------------
// Flash-style window attention, tf32 mma, v2:
//  - double-buffered K/V staging (register-held LDGs overlap compute)
//  - packed mask bits (4 LDG.32/warp/ktile), padded bias prefetched in
//    two groups behind the QK MMA groups (j-outer)
//  - exp2 domain (log2e folded into q-scale and bias)
// ---------------------------------------------------------------------------
#define KTILE   64
#define KSTRIDE 72
#define VSTRIDE 40

__global__ __launch_bounds__(256, 2)
void attn_mma_kernel(const float* __restrict__ qkv,
                     float* __restrict__ out) {
    __shared__ float Kts[2][32 * KSTRIDE];
    __shared__ float Vs[2][KTILE * VSTRIDE];

    const int qt = blockIdx.x;
    const int h  = blockIdx.y;
    const int w  = blockIdx.z;
    const int tid = threadIdx.x, lane = tid & 31, wid = tid >> 5;
    const int g = lane >> 2, t = lane & 3;

    const float* qkvw = qkv + (size_t)w * L_TOK * QKV_N;
    const float* bh = g_bias + (size_t)h * L_TOK * B_STR;
    const uint32_t* mbw = g_mbits + (size_t)w * L_TOK * MW_STR;

    const int rA = qt * 128 + wid * 16 + g;
    const int rB = rA + 8;
    const int rAc = min(rA, L_TOK - 1);
    const int rBc = min(rB, L_TOK - 1);

    // Q fragments, scaled by SCALE_Q * log2e
    const float qs = SCALE_Q * LOG2E_F;
    uint32_t qf[4][4];
#pragma unroll
    for (int kk = 0; kk < 4; kk++) {
        int c0 = h * HEAD_D + kk * 8 + t;
        float a0 = (rA < L_TOK) ? qkvw[(size_t)rA * QKV_N + c0]     * qs : 0.f;
        float a1 = (rB < L_TOK) ? qkvw[(size_t)rB * QKV_N + c0]     * qs : 0.f;
        float a2 = (rA < L_TOK) ? qkvw[(size_t)rA * QKV_N + c0 + 4] * qs : 0.f;
        float a3 = (rB < L_TOK) ? qkvw[(size_t)rB * QKV_N + c0 + 4] * qs : 0.f;
        qf[kk][0] = f2tf32(a0); qf[kk][1] = f2tf32(a1);
        qf[kk][2] = f2tf32(a2); qf[kk][3] = f2tf32(a3);
    }

    float of[4][4];
#pragma unroll
    for (int nt = 0; nt < 4; nt++)
#pragma unroll
        for (int r = 0; r < 4; r++) of[nt][r] = 0.f;

    float mA = -1e30f, mB = -1e30f, sA = 0.f, sB = 0.f;

    // staging helpers: per thread handles rows m = wid + it*8, channel c = lane
    // prologue: stage tile 0
    {
#pragma unroll
        for (int it = 0; it < 8; it++) {
            int m = wid + it * 8;
            int key = m;   // kb = 0
            float kv = (key < L_TOK) ? qkvw[(size_t)key * QKV_N + DIM     + h * HEAD_D + lane] : 0.f;
            float vv = (key < L_TOK) ? qkvw[(size_t)key * QKV_N + 2 * DIM + h * HEAD_D + lane] : 0.f;
            Kts[0][lane * KSTRIDE + m] = __uint_as_float(f2tf32(kv));
            int mr = m & 7;
            int kpos = (m & ~7) | ((mr & 1) ? (mr >> 1) + 4 : (mr >> 1));
            Vs[0][kpos * VSTRIDE + lane] = __uint_as_float(f2tf32(vv));
        }
    }
    __syncthreads();

    for (int kt = 0; kt < 6; kt++) {
        const int kb = kt * KTILE;
        const int cur = kt & 1;

        // issue staging LDGs for next tile (held in regs through compute)
        float avK[8], avV[8];
        if (kt < 5) {
            const int kbn = kb + KTILE;
#pragma unroll
            for (int it = 0; it < 8; it++) {
                int key = kbn + wid + it * 8;
                bool v = (key < L_TOK);
                avK[it] = v ? qkvw[(size_t)key * QKV_N + DIM     + h * HEAD_D + lane] : 0.f;
                avV[it] = v ? qkvw[(size_t)key * QKV_N + 2 * DIM + h * HEAD_D + lane] : 0.f;
            }
        }

        // mask words for this tile (rows rA, rB)
        uint32_t mwA0 = mbw[(size_t)rAc * MW_STR + 2 * kt];
        uint32_t mwA1 = mbw[(size_t)rAc * MW_STR + 2 * kt + 1];
        uint32_t mwB0 = mbw[(size_t)rBc * MW_STR + 2 * kt];
        uint32_t mwB1 = mbw[(size_t)rBc * MW_STR + 2 * kt + 1];

        float sc[8][4];

        // ---- group 0: prefetch bias j=0..3, QK mma j=0..3 ----
        float2 bA[4], bB[4];
#pragma unroll
        for (int j = 0; j < 4; j++) {
            int col = kb + j * 8 + 2 * t;
            bA[j] = *(const float2*)(bh + (size_t)rAc * B_STR + col);
            bB[j] = *(const float2*)(bh + (size_t)rBc * B_STR + col);
        }
#pragma unroll
        for (int j = 0; j < 4; j++) {
#pragma unroll
            for (int r = 0; r < 4; r++) sc[j][r] = 0.f;
#pragma unroll
            for (int kk = 0; kk < 4; kk++) {
                uint32_t b[2];
                b[0] = __float_as_uint(Kts[cur][(kk * 8 + t)     * KSTRIDE + j * 8 + g]);
                b[1] = __float_as_uint(Kts[cur][(kk * 8 + t + 4) * KSTRIDE + j * 8 + g]);
                mma_tf32(sc[j], qf[kk], b);
            }
        }
        // apply bias+mask group 0
#pragma unroll
        for (int j = 0; j < 4; j++) {
            int sh = j * 8 + 2 * t;
            float s0 = sc[j][0] + bA[j].x; if ((mwA0 >> sh) & 1)       s0 = -1e30f;
            float s1 = sc[j][1] + bA[j].y; if ((mwA0 >> (sh + 1)) & 1) s1 = -1e30f;
            float s2 = sc[j][2] + bB[j].x; if ((mwB0 >> sh) & 1)       s2 = -1e30f;
            float s3 = sc[j][3] + bB[j].y; if ((mwB0 >> (sh + 1)) & 1) s3 = -1e30f;
            sc[j][0] = s0; sc[j][1] = s1; sc[j][2] = s2; sc[j][3] = s3;
        }

        // ---- group 1: prefetch bias j=4..7, QK mma j=4..7 ----
#pragma unroll
        for (int j = 0; j < 4; j++) {
            int col = kb + (j + 4) * 8 + 2 * t;
            bA[j] = *(const float2*)(bh + (size_t)rAc * B_STR + col);
            bB[j] = *(const float2*)(bh + (size_t)rBc * B_STR + col);
        }
#pragma unroll
        for (int j = 4; j < 8; j++) {
#pragma unroll
            for (int r = 0; r < 4; r++) sc[j][r] = 0.f;
#pragma unroll
            for (int kk = 0; kk < 4; kk++) {
                uint32_t b[2];
                b[0] = __float_as_uint(Kts[cur][(kk * 8 + t)     * KSTRIDE + j * 8 + g]);
                b[1] = __float_as_uint(Kts[cur][(kk * 8 + t + 4) * KSTRIDE + j * 8 + g]);
                mma_tf32(sc[j], qf[kk], b);
            }
        }
#pragma unroll
        for (int j = 4; j < 8; j++) {
            int sh = (j - 4) * 8 + 2 * t;
            float s0 = sc[j][0] + bA[j - 4].x; if ((mwA1 >> sh) & 1)       s0 = -1e30f;
            float s1 = sc[j][1] + bA[j - 4].y; if ((mwA1 >> (sh + 1)) & 1) s1 = -1e30f;
            float s2 = sc[j][2] + bB[j - 4].x; if ((mwB1 >> sh) & 1)       s2 = -1e30f;
            float s3 = sc[j][3] + bB[j - 4].y; if ((mwB1 >> (sh + 1)) & 1) s3 = -1e30f;
            sc[j][0] = s0; sc[j][1] = s1; sc[j][2] = s2; sc[j][3] = s3;
        }

        // ---- online softmax (log2 domain) ----
        float tmA = -1e30f, tmB = -1e30f;
#pragma unroll
        for (int j = 0; j < 8; j++) {
            tmA = fmaxf(tmA, fmaxf(sc[j][0], sc[j][1]));
            tmB = fmaxf(tmB, fmaxf(sc[j][2], sc[j][3]));
        }
        tmA = fmaxf(tmA, __shfl_xor_sync(0xffffffffu, tmA, 1));
        tmA = fmaxf(tmA, __shfl_xor_sync(0xffffffffu, tmA, 2));
        tmB = fmaxf(tmB, __shfl_xor_sync(0xffffffffu, tmB, 1));
        tmB = fmaxf(tmB, __shfl_xor_sync(0xffffffffu, tmB, 2));

        float mAn = fmaxf(mA, tmA), mBn = fmaxf(mB, tmB);
        float fA = ex2f(mA - mAn), fB = ex2f(mB - mBn);
        mA = mAn; mB = mBn;

        float tsA = 0.f, tsB = 0.f;
#pragma unroll
        for (int j = 0; j < 8; j++) {
            sc[j][0] = ex2f(sc[j][0] - mAn);
            sc[j][1] = ex2f(sc[j][1] - mAn);
            sc[j][2] = ex2f(sc[j][2] - mBn);
            sc[j][3] = ex2f(sc[j][3] - mBn);
            tsA += sc[j][0] + sc[j][1];
            tsB += sc[j][2] + sc[j][3];
        }
        tsA += __shfl_xor_sync(0xffffffffu, tsA, 1);
        tsA += __shfl_xor_sync(0xffffffffu, tsA, 2);
        tsB += __shfl_xor_sync(0xffffffffu, tsB, 1);
        tsB += __shfl_xor_sync(0xffffffffu, tsB, 2);
        sA = sA * fA + tsA;
        sB = sB * fB + tsB;

#pragma unroll
        for (int nt = 0; nt < 4; nt++) {
            of[nt][0] *= fA; of[nt][1] *= fA;
            of[nt][2] *= fB; of[nt][3] *= fB;
        }

        // ---- O += P * V ----
#pragma unroll
        for (int j = 0; j < 8; j++) {
            uint32_t a[4];
            a[0] = f2tf32(sc[j][0]);
            a[1] = f2tf32(sc[j][2]);
            a[2] = f2tf32(sc[j][1]);
            a[3] = f2tf32(sc[j][3]);
#pragma unroll
            for (int nt = 0; nt < 4; nt++) {
                uint32_t b[2];
                b[0] = __float_as_uint(Vs[cur][(j * 8 + t)     * VSTRIDE + nt * 8 + g]);
                b[1] = __float_as_uint(Vs[cur][(j * 8 + t + 4) * VSTRIDE + nt * 8 + g]);
                mma_tf32(of[nt], a, b);
            }
        }

        // ---- stage next tile into the other buffer ----
        if (kt < 5) {
            const int nxt = cur ^ 1;
#pragma unroll
            for (int it = 0; it < 8; it++) {
                int m = wid + it * 8;
                Kts[nxt][lane * KSTRIDE + m] = __uint_as_float(f2tf32(avK[it]));
                int mr = m & 7;
                int kpos = (m & ~7) | ((mr & 1) ? (mr >> 1) + 4 : (mr >> 1));
                Vs[nxt][kpos * VSTRIDE + lane] = __uint_as_float(f2tf32(avV[it]));
            }
        }
        __syncthreads();
    }

    // ---- epilogue ----
    float iA = 1.f / sA, iB = 1.f / sB;
    if (rA < L_TOK) {
        float* op = out + ((size_t)(w * L_TOK + rA)) * DIM + h * HEAD_D;
#pragma unroll
        for (int nt = 0; nt < 4; nt++) {
            float2 v = make_float2(of[nt][0] * iA, of[nt][1] * iA);
            *(float2*)(op + nt * 8 + 2 * t) = v;
        }
    }
    if (rB < L_TOK) {
        float* op = out + ((size_t)(w * L_TOK + rB)) * DIM + h * HEAD_D;
#pragma unroll
        for (int nt = 0; nt < 4; nt++) {
            float2 v = make_float2(of[nt][2] * iB, of[nt][3] * iB);
            *(float2*)(op + nt * 8 + 2 * t) = v;
        }
    }
}

// ---------------------------------------------------------------------------
extern "C" void kernel_launch(void* const* d_in, const int* in_sizes, int n_in,
                              void* d_out, int out_size) {
    const float*        x      = (const float*)d_in[0];
    const float*        qkv_w  = (const float*)d_in[1];
    const float*        table  = (const float*)d_in[2];
    const float*        proj_w = (const float*)d_in[3];
    const float*        proj_b = (const float*)d_in[4];
    const unsigned int* mask   = (const unsigned int*)d_in[5];
    const int*          relidx = (const int*)d_in[6];
    float*              out    = (float*)d_out;

    float* qkv_buf = nullptr;
    float* ao_buf  = nullptr;
    cudaGetSymbolAddress((void**)&qkv_buf, g_qkv);
    cudaGetSymbolAddress((void**)&ao_buf,  g_attn_out);

    cudaFuncSetAttribute(tf32_gemm_kernel,
                         cudaFuncAttributeMaxDynamicSharedMemorySize,
                         G_SMEM_BYTES);

    // 0) padded bias precompute + mask bit-packing
    {
        int total = N_HEAD * L_TOK * B_STR;
        bias_kernel<<<(total + 255) / 256, 256>>>(table, relidx);
        int rows = N_WIN * L_TOK;            // one warp per row
        maskpack_kernel<<<(rows * 32 + 255) / 256, 256>>>(mask);
    }

    // 1) QKV GEMM: (21952 x 384) @ (384 x 1152), tf32 tensor cores
    {
        dim3 grid(QKV_N / G_BN, (M_ROWS + G_BM - 1) / G_BM);
        tf32_gemm_kernel<<<grid, 256, G_SMEM_BYTES>>>(x, qkv_w, nullptr, qkv_buf,
                                                      M_ROWS, QKV_N, DIM);
    }

    // 2) Attention: tf32 mma flash-style v2
    {
        dim3 grid(3, N_HEAD, N_WIN);
        attn_mma_kernel<<<grid, 256>>>(qkv_buf, ao_buf);
    }

    // 3) Projection GEMM + bias: (21952 x 384) @ (384 x 384) + b, tf32
    {
        dim3 grid(DIM / G_BN, (M_ROWS + G_BM - 1) / G_BM);
        tf32_gemm_kernel<<<grid, 256, G_SMEM_BYTES>>>(ao_buf, proj_w, proj_b, out,
                                                      M_ROWS, DIM, DIM);
    }
}